// round 1
// baseline (speedup 1.0000x reference)
#include <cuda_runtime.h>
#include <math.h>

// Problem constants
#define Bb  2
#define Ss  2048
#define Dd  1024
#define Hh  16
#define HDd 64
#define Tt  (Bb*Ss)   // 4096 tokens
#define E3  (3*Dd)    // 3072

// Scratch (device globals — no allocations allowed)
__device__ float g_q[(size_t)Bb*Hh*Ss*HDd];   // [b][h][s][hd]
__device__ float g_k[(size_t)Bb*Hh*Ss*HDd];
__device__ float g_v[(size_t)Bb*Hh*Ss*HDd];
__device__ float g_o[(size_t)Tt*Dd];          // [t][d]
__device__ float g_cos[Ss*32];
__device__ float g_sin[Ss*32];

// ---------------------------------------------------------------------------
// Kernel 0: RoPE cos/sin table. theta_j = 10000^(-j/32), angle = s*theta.
// Computed in double for accuracy, stored fp32 (matches fp32 reference to ~1e-4).
// ---------------------------------------------------------------------------
__global__ void rope_table_kernel() {
    int idx = blockIdx.x * blockDim.x + threadIdx.x;
    if (idx >= Ss * 32) return;
    int s = idx >> 5;
    int j = idx & 31;
    double theta = exp(-((double)j / 32.0) * log(10000.0));
    double a = (double)s * theta;
    g_cos[idx] = (float)cos(a);
    g_sin[idx] = (float)sin(a);
}

// ---------------------------------------------------------------------------
// Kernel 1: QKV GEMM + RoPE + scatter.
// C[t][e] = sum_d X[t][d] * W[e][d]   (t<4096, e<3072, d<1024)
// Tiles: BM=128, BN=128, BK=16, 256 threads, 8x8 per thread.
// Epilogue: stage 128x64 halves through smem so RoPE partner (c ^ 32) is
// visible, then scatter to g_q/g_k/g_v in [b][h][s][hd] layout.
// ---------------------------------------------------------------------------
__global__ __launch_bounds__(256)
void qkv_rope_kernel(const float* __restrict__ X, const float* __restrict__ W) {
    __shared__ float sA[16][128];
    __shared__ float sB[16][128];
    __shared__ float sC[128][64];   // total static smem = 49152B exactly

    const int tid = threadIdx.x;
    const int m0 = blockIdx.y * 128;
    const int n0 = blockIdx.x * 128;
    const int tx = tid & 15;        // col group (8 cols)
    const int ty = tid >> 4;        // row group (8 rows)
    const int lr = tid >> 2;        // load row 0..63
    const int lc = (tid & 3) << 2;  // load col (float4) 0,4,8,12

    float acc[8][8];
    #pragma unroll
    for (int i = 0; i < 8; i++)
        #pragma unroll
        for (int j = 0; j < 8; j++) acc[i][j] = 0.0f;

    for (int k0 = 0; k0 < 1024; k0 += 16) {
        #pragma unroll
        for (int hh = 0; hh < 2; hh++) {
            int row = lr + hh * 64;
            float4 va = *(const float4*)(X + (size_t)(m0 + row) * 1024 + k0 + lc);
            sA[lc + 0][row] = va.x; sA[lc + 1][row] = va.y;
            sA[lc + 2][row] = va.z; sA[lc + 3][row] = va.w;
            float4 vb = *(const float4*)(W + (size_t)(n0 + row) * 1024 + k0 + lc);
            sB[lc + 0][row] = vb.x; sB[lc + 1][row] = vb.y;
            sB[lc + 2][row] = vb.z; sB[lc + 3][row] = vb.w;
        }
        __syncthreads();
        #pragma unroll 4
        for (int kk = 0; kk < 16; kk++) {
            float a[8], b[8];
            *(float4*)&a[0] = *(const float4*)&sA[kk][ty * 8];
            *(float4*)&a[4] = *(const float4*)&sA[kk][ty * 8 + 4];
            *(float4*)&b[0] = *(const float4*)&sB[kk][tx * 8];
            *(float4*)&b[4] = *(const float4*)&sB[kk][tx * 8 + 4];
            #pragma unroll
            for (int i = 0; i < 8; i++)
                #pragma unroll
                for (int j = 0; j < 8; j++) acc[i][j] += a[i] * b[j];
        }
        __syncthreads();
    }

    // Epilogue: two 64-col halves. Each half fully contains RoPE pairs (c^32).
    #pragma unroll
    for (int hh = 0; hh < 2; hh++) {
        if ((tx >> 3) == hh) {
            int cb = (tx & 7) * 8;
            #pragma unroll
            for (int i = 0; i < 8; i++)
                #pragma unroll
                for (int j = 0; j < 8; j++) sC[ty * 8 + i][cb + j] = acc[i][j];
        }
        __syncthreads();
        for (int e = tid; e < 128 * 64; e += 256) {
            int r = e >> 6;
            int c = e & 63;
            int t = m0 + r;
            int b = t >> 11;          // / Ss
            int s = t & 2047;         // % Ss
            int col = n0 + hh * 64 + c;
            int head = col >> 6;      // 0..47
            float v = sC[r][c];
            float outv = v;
            if (head < 32) {
                float part = sC[r][c ^ 32];
                float rot = (c < 32) ? -part : part;
                float cs = g_cos[(s << 5) + (c & 31)];
                float sn = g_sin[(s << 5) + (c & 31)];
                outv = v * cs + rot * sn;
            }
            // scatter to [b][h][s][hd]
            if (head < 16)
                g_q[(((size_t)(b * Hh + head)      << 11) + s) * 64 + c] = outv;
            else if (head < 32)
                g_k[(((size_t)(b * Hh + head - 16) << 11) + s) * 64 + c] = outv;
            else
                g_v[(((size_t)(b * Hh + head - 32) << 11) + s) * 64 + c] = outv;
        }
        __syncthreads();
    }
}

// ---------------------------------------------------------------------------
// Kernel 2: causal flash attention, fp32.
// Grid: (S/64, B*H). Block 256 threads; each thread owns a 4x4 micro-tile.
// Smem (dynamic, 51200B): sQt[64][68] (k-major Q), sKt[64][68] (k-major K,
// later aliased as P[r][j]), sV[64][64].
// ---------------------------------------------------------------------------
__global__ __launch_bounds__(256)
void attn_kernel() {
    extern __shared__ float dsm[];
    float* sQt = dsm;                 // [k][r], stride 68
    float* sKt = dsm + 64 * 68;       // [k][c], stride 68; aliased as P[r*68+j]
    float* sV  = dsm + 2 * 64 * 68;   // [j][c], stride 64

    const int tid = threadIdx.x;
    const int bh = blockIdx.y;
    const int q0 = blockIdx.x * 64;
    const int b = bh >> 4;
    const int h = bh & 15;

    const float* Qb = g_q + ((size_t)bh * Ss + q0) * 64;

    for (int idx = tid; idx < 64 * 64; idx += 256) {
        int r = idx >> 6, c = idx & 63;
        sQt[c * 68 + r] = Qb[idx];
    }

    const int tx = tid & 15;   // key/headdim col group
    const int ty = tid >> 4;   // query row group

    float o_acc[4][4];
    float m_prev[4], l_acc[4];
    #pragma unroll
    for (int i = 0; i < 4; i++) {
        m_prev[i] = -1e30f;
        l_acc[i] = 0.0f;
        #pragma unroll
        for (int j = 0; j < 4; j++) o_acc[i][j] = 0.0f;
    }
    __syncthreads();

    for (int kv0 = 0; kv0 <= q0; kv0 += 64) {
        const float* Kb = g_k + ((size_t)bh * Ss + kv0) * 64;
        const float* Vb = g_v + ((size_t)bh * Ss + kv0) * 64;
        for (int idx = tid; idx < 64 * 64; idx += 256) {
            int r = idx >> 6, c = idx & 63;
            sKt[c * 68 + r] = Kb[idx];
            sV[idx] = Vb[idx];
        }
        __syncthreads();

        // S = Q K^T (outer product over hd)
        float sc[4][4];
        #pragma unroll
        for (int i = 0; i < 4; i++)
            #pragma unroll
            for (int j = 0; j < 4; j++) sc[i][j] = 0.0f;

        #pragma unroll 8
        for (int kk = 0; kk < 64; kk++) {
            float4 a4 = *(const float4*)(sQt + kk * 68 + ty * 4);
            float4 b4 = *(const float4*)(sKt + kk * 68 + tx * 4);
            float av[4] = {a4.x, a4.y, a4.z, a4.w};
            float bv[4] = {b4.x, b4.y, b4.z, b4.w};
            #pragma unroll
            for (int i = 0; i < 4; i++)
                #pragma unroll
                for (int j = 0; j < 4; j++) sc[i][j] += av[i] * bv[j];
        }
        __syncthreads();   // done reading sKt (about to overwrite with P)

        // scale + causal mask (only diagonal tile needs the mask)
        const bool diag = (kv0 == q0);
        #pragma unroll
        for (int i = 0; i < 4; i++)
            #pragma unroll
            for (int j = 0; j < 4; j++) {
                float v = sc[i][j] * 0.125f;
                if (diag && (kv0 + tx * 4 + j > q0 + ty * 4 + i)) v = -1e30f;
                sc[i][j] = v;
            }

        // row max across the 16 lanes sharing ty
        float mt[4];
        #pragma unroll
        for (int i = 0; i < 4; i++) {
            mt[i] = fmaxf(fmaxf(sc[i][0], sc[i][1]), fmaxf(sc[i][2], sc[i][3]));
        }
        #pragma unroll
        for (int w = 1; w < 16; w <<= 1) {
            #pragma unroll
            for (int i = 0; i < 4; i++)
                mt[i] = fmaxf(mt[i], __shfl_xor_sync(0xffffffffu, mt[i], w));
        }

        float mnew[4], alpha[4], p[4][4], rs[4];
        #pragma unroll
        for (int i = 0; i < 4; i++) {
            mnew[i] = fmaxf(m_prev[i], mt[i]);
            alpha[i] = expf(m_prev[i] - mnew[i]);
            rs[i] = 0.0f;
            #pragma unroll
            for (int j = 0; j < 4; j++) {
                p[i][j] = expf(sc[i][j] - mnew[i]);
                rs[i] += p[i][j];
            }
            m_prev[i] = mnew[i];
        }
        #pragma unroll
        for (int w = 1; w < 16; w <<= 1) {
            #pragma unroll
            for (int i = 0; i < 4; i++)
                rs[i] += __shfl_xor_sync(0xffffffffu, rs[i], w);
        }
        #pragma unroll
        for (int i = 0; i < 4; i++) {
            l_acc[i] = l_acc[i] * alpha[i] + rs[i];
            #pragma unroll
            for (int j = 0; j < 4; j++) o_acc[i][j] *= alpha[i];
        }

        // write P into sKt region: P[r][j], stride 68
        #pragma unroll
        for (int i = 0; i < 4; i++)
            #pragma unroll
            for (int j = 0; j < 4; j++)
                sKt[(ty * 4 + i) * 68 + tx * 4 + j] = p[i][j];
        __syncthreads();

        // O += P V (outer product over key index j)
        #pragma unroll 8
        for (int j = 0; j < 64; j++) {
            float av[4];
            #pragma unroll
            for (int i = 0; i < 4; i++) av[i] = sKt[(ty * 4 + i) * 68 + j];
            float4 b4 = *(const float4*)(sV + j * 64 + tx * 4);
            float bv[4] = {b4.x, b4.y, b4.z, b4.w};
            #pragma unroll
            for (int i = 0; i < 4; i++)
                #pragma unroll
                for (int jj = 0; jj < 4; jj++) o_acc[i][jj] += av[i] * bv[jj];
        }
        __syncthreads();   // protect sKt/sV before next tile load
    }

    // normalize + write to g_o[t][d]
    #pragma unroll
    for (int i = 0; i < 4; i++) {
        float inv = 1.0f / l_acc[i];
        int s = q0 + ty * 4 + i;
        #pragma unroll
        for (int jj = 0; jj < 4; jj++)
            g_o[((size_t)(b * Ss + s)) * 1024 + h * 64 + tx * 4 + jj] =
                o_acc[i][jj] * inv;
    }
}

// ---------------------------------------------------------------------------
// Kernel 3: output projection + bias. out[t][e] = sum_d o[t][d]*W[e][d] + b[e]
// Same tiling as kernel 1, simple register epilogue.
// ---------------------------------------------------------------------------
__global__ __launch_bounds__(256)
void proj_kernel(const float* __restrict__ W, const float* __restrict__ bias,
                 float* __restrict__ out) {
    __shared__ float sA[16][128];
    __shared__ float sB[16][128];

    const int tid = threadIdx.x;
    const int m0 = blockIdx.y * 128;
    const int n0 = blockIdx.x * 128;
    const int tx = tid & 15;
    const int ty = tid >> 4;
    const int lr = tid >> 2;
    const int lc = (tid & 3) << 2;

    float acc[8][8];
    #pragma unroll
    for (int i = 0; i < 8; i++)
        #pragma unroll
        for (int j = 0; j < 8; j++) acc[i][j] = 0.0f;

    for (int k0 = 0; k0 < 1024; k0 += 16) {
        #pragma unroll
        for (int hh = 0; hh < 2; hh++) {
            int row = lr + hh * 64;
            float4 va = *(const float4*)(g_o + (size_t)(m0 + row) * 1024 + k0 + lc);
            sA[lc + 0][row] = va.x; sA[lc + 1][row] = va.y;
            sA[lc + 2][row] = va.z; sA[lc + 3][row] = va.w;
            float4 vb = *(const float4*)(W + (size_t)(n0 + row) * 1024 + k0 + lc);
            sB[lc + 0][row] = vb.x; sB[lc + 1][row] = vb.y;
            sB[lc + 2][row] = vb.z; sB[lc + 3][row] = vb.w;
        }
        __syncthreads();
        #pragma unroll 4
        for (int kk = 0; kk < 16; kk++) {
            float a[8], b[8];
            *(float4*)&a[0] = *(const float4*)&sA[kk][ty * 8];
            *(float4*)&a[4] = *(const float4*)&sA[kk][ty * 8 + 4];
            *(float4*)&b[0] = *(const float4*)&sB[kk][tx * 8];
            *(float4*)&b[4] = *(const float4*)&sB[kk][tx * 8 + 4];
            #pragma unroll
            for (int i = 0; i < 8; i++)
                #pragma unroll
                for (int j = 0; j < 8; j++) acc[i][j] += a[i] * b[j];
        }
        __syncthreads();
    }

    #pragma unroll
    for (int j = 0; j < 8; j++) {
        float bj = bias[n0 + tx * 8 + j];
        #pragma unroll
        for (int i = 0; i < 8; i++)
            out[(size_t)(m0 + ty * 8 + i) * 1024 + n0 + tx * 8 + j] =
                acc[i][j] + bj;
    }
}

// ---------------------------------------------------------------------------
extern "C" void kernel_launch(void* const* d_in, const int* in_sizes, int n_in,
                              void* d_out, int out_size) {
    const float* x     = (const float*)d_in[0];
    const float* w_qkv = (const float*)d_in[1];
    const float* w_out = (const float*)d_in[2];
    const float* b_out = (const float*)d_in[3];
    float* out = (float*)d_out;

    rope_table_kernel<<<(Ss * 32 + 255) / 256, 256>>>();

    dim3 g1(E3 / 128, Tt / 128);
    qkv_rope_kernel<<<g1, 256>>>(x, w_qkv);

    const int attn_smem = (2 * 64 * 68 + 64 * 64) * (int)sizeof(float); // 51200
    cudaFuncSetAttribute(attn_kernel,
                         cudaFuncAttributeMaxDynamicSharedMemorySize, attn_smem);
    attn_kernel<<<dim3(Ss / 64, Bb * Hh), 256, attn_smem>>>();

    proj_kernel<<<dim3(Dd / 128, Tt / 128), 256>>>(w_out, b_out, out);
}

// round 2
// speedup vs baseline: 2.7117x; 2.7117x over previous
#include <cuda_runtime.h>
#include <math.h>
#include <stdint.h>

// Problem constants
#define Bb  2
#define Ss  2048
#define Dd  1024
#define Hh  16
#define HDd 64
#define Tt  (Bb*Ss)   // 4096 tokens
#define E3  (3*Dd)    // 3072

// Scratch (device globals — no allocations allowed)
__device__ float g_q[(size_t)Bb*Hh*Ss*HDd];   // [b][h][s][hd]
__device__ float g_k[(size_t)Bb*Hh*Ss*HDd];
__device__ float g_v[(size_t)Bb*Hh*Ss*HDd];
__device__ float g_o[(size_t)Tt*Dd];          // [t][d]
__device__ float g_cos[Ss*32];
__device__ float g_sin[Ss*32];

// ---------------------------------------------------------------------------
// tf32 helpers
// ---------------------------------------------------------------------------
__device__ __forceinline__ uint32_t f2tf(float f) {
    uint32_t r;
    asm("cvt.rna.tf32.f32 %0, %1;" : "=r"(r) : "f"(f));
    return r;
}

__device__ __forceinline__ void mma_tf32(float c[4],
                                         const uint32_t a[4],
                                         const uint32_t b[2]) {
    asm volatile(
        "mma.sync.aligned.m16n8k8.row.col.f32.tf32.tf32.f32 "
        "{%0,%1,%2,%3},{%4,%5,%6,%7},{%8,%9},{%0,%1,%2,%3};\n"
        : "+f"(c[0]), "+f"(c[1]), "+f"(c[2]), "+f"(c[3])
        : "r"(a[0]), "r"(a[1]), "r"(a[2]), "r"(a[3]),
          "r"(b[0]), "r"(b[1]));
}

// ---------------------------------------------------------------------------
// Kernel 0: RoPE cos/sin table (double precision, stored fp32)
// ---------------------------------------------------------------------------
__global__ void rope_table_kernel() {
    int idx = blockIdx.x * blockDim.x + threadIdx.x;
    if (idx >= Ss * 32) return;
    int s = idx >> 5;
    int j = idx & 31;
    double theta = exp(-((double)j / 32.0) * log(10000.0));
    double a = (double)s * theta;
    g_cos[idx] = (float)cos(a);
    g_sin[idx] = (float)sin(a);
}

// ---------------------------------------------------------------------------
// Shared GEMM core: C[128x128] = A[m0:+128, :K] * B[n0:+128, :K]^T  via tf32 mma.
// 256 threads = 8 warps in 2(m) x 4(n) grid; warp tile 64x32;
// per warp: 4 m-atoms (m16) x 4 n-atoms (n8), k in steps of 8.
// smem tiles: sA/sB [128][36] (tf32 bits), padded stride 36.
// ---------------------------------------------------------------------------
#define SM_STRIDE 36

__device__ __forceinline__ void gemm_core_tf32(
    const float* __restrict__ A, const float* __restrict__ B,
    int m0, int n0, int K,
    uint32_t* __restrict__ sA, uint32_t* __restrict__ sB,
    float acc[4][4][4])
{
    const int tid  = threadIdx.x;
    const int warp = tid >> 5;
    const int lane = tid & 31;
    const int wm   = warp >> 2;   // 0..1
    const int wn   = warp & 3;    // 0..3
    const int grp  = lane >> 2;   // 0..7
    const int tg   = lane & 3;    // 0..3

    const int lrow = tid >> 3;         // 0..31
    const int lcol = (tid & 7) << 2;   // 0,4,...,28

    for (int k0 = 0; k0 < K; k0 += 32) {
        // Load + convert global -> tf32 smem
        #pragma unroll
        for (int it = 0; it < 4; it++) {
            int row = lrow + it * 32;
            float4 va = *(const float4*)(A + (size_t)(m0 + row) * K + k0 + lcol);
            uint4 ua = make_uint4(f2tf(va.x), f2tf(va.y), f2tf(va.z), f2tf(va.w));
            *(uint4*)(sA + row * SM_STRIDE + lcol) = ua;
            float4 vb = *(const float4*)(B + (size_t)(n0 + row) * K + k0 + lcol);
            uint4 ub = make_uint4(f2tf(vb.x), f2tf(vb.y), f2tf(vb.z), f2tf(vb.w));
            *(uint4*)(sB + row * SM_STRIDE + lcol) = ub;
        }
        __syncthreads();

        #pragma unroll
        for (int ka = 0; ka < 4; ka++) {
            const int kb = ka * 8;
            uint32_t af[4][4], bf[4][2];
            #pragma unroll
            for (int ma = 0; ma < 4; ma++) {
                int r = wm * 64 + ma * 16 + grp;
                af[ma][0] = sA[r * SM_STRIDE + kb + tg];
                af[ma][1] = sA[(r + 8) * SM_STRIDE + kb + tg];
                af[ma][2] = sA[r * SM_STRIDE + kb + tg + 4];
                af[ma][3] = sA[(r + 8) * SM_STRIDE + kb + tg + 4];
            }
            #pragma unroll
            for (int na = 0; na < 4; na++) {
                int c = wn * 32 + na * 8 + grp;
                bf[na][0] = sB[c * SM_STRIDE + kb + tg];
                bf[na][1] = sB[c * SM_STRIDE + kb + tg + 4];
            }
            #pragma unroll
            for (int ma = 0; ma < 4; ma++)
                #pragma unroll
                for (int na = 0; na < 4; na++)
                    mma_tf32(acc[ma][na], af[ma], bf[na]);
        }
        __syncthreads();
    }
}

// ---------------------------------------------------------------------------
// Kernel 1: QKV GEMM (tf32 mma) + RoPE + scatter to [b][h][s][hd]
// Dynamic smem: 2 * 128 * 36 * 4 = 36864 B; epilogue aliases it as sC[128][64].
// ---------------------------------------------------------------------------
__global__ __launch_bounds__(256)
void qkv_rope_kernel(const float* __restrict__ X, const float* __restrict__ W) {
    extern __shared__ uint32_t dsm_u[];
    uint32_t* sA = dsm_u;
    uint32_t* sB = dsm_u + 128 * SM_STRIDE;
    float* sC = (float*)dsm_u;   // 128*64 floats = 32768 B, fits

    const int tid = threadIdx.x;
    const int m0 = blockIdx.y * 128;
    const int n0 = blockIdx.x * 128;
    const int warp = tid >> 5;
    const int lane = tid & 31;
    const int wm = warp >> 2, wn = warp & 3;
    const int grp = lane >> 2, tg = lane & 3;

    float acc[4][4][4];
    #pragma unroll
    for (int i = 0; i < 4; i++)
        #pragma unroll
        for (int j = 0; j < 4; j++)
            #pragma unroll
            for (int v = 0; v < 4; v++) acc[i][j][v] = 0.0f;

    gemm_core_tf32(X, W, m0, n0, 1024, sA, sB, acc);
    // core ends with __syncthreads(): smem free to reuse

    #pragma unroll
    for (int hh = 0; hh < 2; hh++) {
        if ((wn >> 1) == hh) {
            #pragma unroll
            for (int ma = 0; ma < 4; ma++) {
                int row = wm * 64 + ma * 16 + grp;
                #pragma unroll
                for (int na = 0; na < 4; na++) {
                    int col = (wn & 1) * 32 + na * 8 + 2 * tg;
                    *(float2*)(sC + row * 64 + col) =
                        make_float2(acc[ma][na][0], acc[ma][na][1]);
                    *(float2*)(sC + (row + 8) * 64 + col) =
                        make_float2(acc[ma][na][2], acc[ma][na][3]);
                }
            }
        }
        __syncthreads();

        for (int e = tid; e < 128 * 64; e += 256) {
            int r = e >> 6;
            int c = e & 63;
            int t = m0 + r;
            int b = t >> 11;
            int s = t & 2047;
            int col = n0 + hh * 64 + c;
            int head = col >> 6;      // 0..47
            float v = sC[r * 64 + c];
            float outv = v;
            if (head < 32) {
                float part = sC[r * 64 + (c ^ 32)];
                float rot = (c < 32) ? -part : part;
                float cs = g_cos[(s << 5) + (c & 31)];
                float sn = g_sin[(s << 5) + (c & 31)];
                outv = v * cs + rot * sn;
            }
            if (head < 16)
                g_q[(((size_t)(b * Hh + head)      << 11) + s) * 64 + c] = outv;
            else if (head < 32)
                g_k[(((size_t)(b * Hh + head - 16) << 11) + s) * 64 + c] = outv;
            else
                g_v[(((size_t)(b * Hh + head - 32) << 11) + s) * 64 + c] = outv;
        }
        __syncthreads();
    }
}

// ---------------------------------------------------------------------------
// Kernel 3: output projection + bias via tf32 mma. Direct register epilogue.
// ---------------------------------------------------------------------------
__global__ __launch_bounds__(256)
void proj_kernel(const float* __restrict__ W, const float* __restrict__ bias,
                 float* __restrict__ out) {
    extern __shared__ uint32_t dsm_u[];
    uint32_t* sA = dsm_u;
    uint32_t* sB = dsm_u + 128 * SM_STRIDE;

    const int tid = threadIdx.x;
    const int m0 = blockIdx.y * 128;
    const int n0 = blockIdx.x * 128;
    const int warp = tid >> 5;
    const int lane = tid & 31;
    const int wm = warp >> 2, wn = warp & 3;
    const int grp = lane >> 2, tg = lane & 3;

    float acc[4][4][4];
    #pragma unroll
    for (int i = 0; i < 4; i++)
        #pragma unroll
        for (int j = 0; j < 4; j++)
            #pragma unroll
            for (int v = 0; v < 4; v++) acc[i][j][v] = 0.0f;

    gemm_core_tf32(g_o, W, m0, n0, 1024, sA, sB, acc);

    #pragma unroll
    for (int ma = 0; ma < 4; ma++) {
        int row = m0 + wm * 64 + ma * 16 + grp;
        #pragma unroll
        for (int na = 0; na < 4; na++) {
            int col = n0 + wn * 32 + na * 8 + 2 * tg;
            float b0 = bias[col], b1 = bias[col + 1];
            *(float2*)(out + (size_t)row * 1024 + col) =
                make_float2(acc[ma][na][0] + b0, acc[ma][na][1] + b1);
            *(float2*)(out + (size_t)(row + 8) * 1024 + col) =
                make_float2(acc[ma][na][2] + b0, acc[ma][na][3] + b1);
        }
    }
}

// ---------------------------------------------------------------------------
// Kernel 2: causal flash attention, fp32 SIMT (unchanged from R1).
// ---------------------------------------------------------------------------
__global__ __launch_bounds__(256)
void attn_kernel() {
    extern __shared__ float dsm[];
    float* sQt = dsm;                 // [k][r], stride 68
    float* sKt = dsm + 64 * 68;       // [k][c], stride 68; aliased as P
    float* sV  = dsm + 2 * 64 * 68;   // [j][c], stride 64

    const int tid = threadIdx.x;
    const int bh = blockIdx.y;
    const int q0 = blockIdx.x * 64;
    const int b = bh >> 4;
    const int h = bh & 15;

    const float* Qb = g_q + ((size_t)bh * Ss + q0) * 64;

    for (int idx = tid; idx < 64 * 64; idx += 256) {
        int r = idx >> 6, c = idx & 63;
        sQt[c * 68 + r] = Qb[idx];
    }

    const int tx = tid & 15;
    const int ty = tid >> 4;

    float o_acc[4][4];
    float m_prev[4], l_acc[4];
    #pragma unroll
    for (int i = 0; i < 4; i++) {
        m_prev[i] = -1e30f;
        l_acc[i] = 0.0f;
        #pragma unroll
        for (int j = 0; j < 4; j++) o_acc[i][j] = 0.0f;
    }
    __syncthreads();

    for (int kv0 = 0; kv0 <= q0; kv0 += 64) {
        const float* Kb = g_k + ((size_t)bh * Ss + kv0) * 64;
        const float* Vb = g_v + ((size_t)bh * Ss + kv0) * 64;
        for (int idx = tid; idx < 64 * 64; idx += 256) {
            int r = idx >> 6, c = idx & 63;
            sKt[c * 68 + r] = Kb[idx];
            sV[idx] = Vb[idx];
        }
        __syncthreads();

        float sc[4][4];
        #pragma unroll
        for (int i = 0; i < 4; i++)
            #pragma unroll
            for (int j = 0; j < 4; j++) sc[i][j] = 0.0f;

        #pragma unroll 8
        for (int kk = 0; kk < 64; kk++) {
            float4 a4 = *(const float4*)(sQt + kk * 68 + ty * 4);
            float4 b4 = *(const float4*)(sKt + kk * 68 + tx * 4);
            float av[4] = {a4.x, a4.y, a4.z, a4.w};
            float bv[4] = {b4.x, b4.y, b4.z, b4.w};
            #pragma unroll
            for (int i = 0; i < 4; i++)
                #pragma unroll
                for (int j = 0; j < 4; j++) sc[i][j] += av[i] * bv[j];
        }
        __syncthreads();

        const bool diag = (kv0 == q0);
        #pragma unroll
        for (int i = 0; i < 4; i++)
            #pragma unroll
            for (int j = 0; j < 4; j++) {
                float v = sc[i][j] * 0.125f;
                if (diag && (kv0 + tx * 4 + j > q0 + ty * 4 + i)) v = -1e30f;
                sc[i][j] = v;
            }

        float mt[4];
        #pragma unroll
        for (int i = 0; i < 4; i++)
            mt[i] = fmaxf(fmaxf(sc[i][0], sc[i][1]), fmaxf(sc[i][2], sc[i][3]));
        #pragma unroll
        for (int w = 1; w < 16; w <<= 1) {
            #pragma unroll
            for (int i = 0; i < 4; i++)
                mt[i] = fmaxf(mt[i], __shfl_xor_sync(0xffffffffu, mt[i], w));
        }

        float mnew[4], alpha[4], p[4][4], rs[4];
        #pragma unroll
        for (int i = 0; i < 4; i++) {
            mnew[i] = fmaxf(m_prev[i], mt[i]);
            alpha[i] = expf(m_prev[i] - mnew[i]);
            rs[i] = 0.0f;
            #pragma unroll
            for (int j = 0; j < 4; j++) {
                p[i][j] = expf(sc[i][j] - mnew[i]);
                rs[i] += p[i][j];
            }
            m_prev[i] = mnew[i];
        }
        #pragma unroll
        for (int w = 1; w < 16; w <<= 1) {
            #pragma unroll
            for (int i = 0; i < 4; i++)
                rs[i] += __shfl_xor_sync(0xffffffffu, rs[i], w);
        }
        #pragma unroll
        for (int i = 0; i < 4; i++) {
            l_acc[i] = l_acc[i] * alpha[i] + rs[i];
            #pragma unroll
            for (int j = 0; j < 4; j++) o_acc[i][j] *= alpha[i];
        }

        #pragma unroll
        for (int i = 0; i < 4; i++)
            #pragma unroll
            for (int j = 0; j < 4; j++)
                sKt[(ty * 4 + i) * 68 + tx * 4 + j] = p[i][j];
        __syncthreads();

        #pragma unroll 8
        for (int j = 0; j < 64; j++) {
            float av[4];
            #pragma unroll
            for (int i = 0; i < 4; i++) av[i] = sKt[(ty * 4 + i) * 68 + j];
            float4 b4 = *(const float4*)(sV + j * 64 + tx * 4);
            float bv[4] = {b4.x, b4.y, b4.z, b4.w};
            #pragma unroll
            for (int i = 0; i < 4; i++)
                #pragma unroll
                for (int jj = 0; jj < 4; jj++) o_acc[i][jj] += av[i] * bv[jj];
        }
        __syncthreads();
    }

    #pragma unroll
    for (int i = 0; i < 4; i++) {
        float inv = 1.0f / l_acc[i];
        int s = q0 + ty * 4 + i;
        #pragma unroll
        for (int jj = 0; jj < 4; jj++)
            g_o[((size_t)(b * Ss + s)) * 1024 + h * 64 + tx * 4 + jj] =
                o_acc[i][jj] * inv;
    }
}

// ---------------------------------------------------------------------------
extern "C" void kernel_launch(void* const* d_in, const int* in_sizes, int n_in,
                              void* d_out, int out_size) {
    const float* x     = (const float*)d_in[0];
    const float* w_qkv = (const float*)d_in[1];
    const float* w_out = (const float*)d_in[2];
    const float* b_out = (const float*)d_in[3];
    float* out = (float*)d_out;

    rope_table_kernel<<<(Ss * 32 + 255) / 256, 256>>>();

    const int gemm_smem = 2 * 128 * SM_STRIDE * (int)sizeof(uint32_t); // 36864
    qkv_rope_kernel<<<dim3(E3 / 128, Tt / 128), 256, gemm_smem>>>(x, w_qkv);

    const int attn_smem = (2 * 64 * 68 + 64 * 64) * (int)sizeof(float); // 51200
    cudaFuncSetAttribute(attn_kernel,
                         cudaFuncAttributeMaxDynamicSharedMemorySize, attn_smem);
    attn_kernel<<<dim3(Ss / 64, Bb * Hh), 256, attn_smem>>>();

    proj_kernel<<<dim3(Dd / 128, Tt / 128), 256, gemm_smem>>>(w_out, b_out, out);
}

// round 3
// speedup vs baseline: 4.6625x; 1.7194x over previous
#include <cuda_runtime.h>
#include <math.h>
#include <stdint.h>

// Problem constants
#define Bb  2
#define Ss  2048
#define Dd  1024
#define Hh  16
#define HDd 64
#define Tt  (Bb*Ss)   // 4096 tokens
#define E3  (3*Dd)    // 3072

// Scratch (device globals — no allocations allowed)
__device__ float g_q[(size_t)Bb*Hh*Ss*HDd];   // [b][h][s][hd]
__device__ float g_k[(size_t)Bb*Hh*Ss*HDd];
__device__ float g_v[(size_t)Bb*Hh*Ss*HDd];
__device__ float g_o[(size_t)Tt*Dd];          // [t][d]
__device__ float g_cos[Ss*32];
__device__ float g_sin[Ss*32];

// ---------------------------------------------------------------------------
// tf32 helpers
// ---------------------------------------------------------------------------
__device__ __forceinline__ uint32_t f2tf(float f) {
    uint32_t r;
    asm("cvt.rna.tf32.f32 %0, %1;" : "=r"(r) : "f"(f));
    return r;
}

__device__ __forceinline__ void mma_tf32(float c[4],
                                         const uint32_t a[4],
                                         const uint32_t b[2]) {
    asm volatile(
        "mma.sync.aligned.m16n8k8.row.col.f32.tf32.tf32.f32 "
        "{%0,%1,%2,%3},{%4,%5,%6,%7},{%8,%9},{%0,%1,%2,%3};\n"
        : "+f"(c[0]), "+f"(c[1]), "+f"(c[2]), "+f"(c[3])
        : "r"(a[0]), "r"(a[1]), "r"(a[2]), "r"(a[3]),
          "r"(b[0]), "r"(b[1]));
}

// ---------------------------------------------------------------------------
// Kernel 0: RoPE cos/sin table (double precision, stored fp32)
// ---------------------------------------------------------------------------
__global__ void rope_table_kernel() {
    int idx = blockIdx.x * blockDim.x + threadIdx.x;
    if (idx >= Ss * 32) return;
    int s = idx >> 5;
    int j = idx & 31;
    double theta = exp(-((double)j / 32.0) * log(10000.0));
    double a = (double)s * theta;
    g_cos[idx] = (float)cos(a);
    g_sin[idx] = (float)sin(a);
}

// ---------------------------------------------------------------------------
// Shared GEMM core (unchanged from R2): C = A * B^T via tf32 mma, 128x128 tile.
// ---------------------------------------------------------------------------
#define SM_STRIDE 36

__device__ __forceinline__ void gemm_core_tf32(
    const float* __restrict__ A, const float* __restrict__ B,
    int m0, int n0, int K,
    uint32_t* __restrict__ sA, uint32_t* __restrict__ sB,
    float acc[4][4][4])
{
    const int tid  = threadIdx.x;
    const int warp = tid >> 5;
    const int lane = tid & 31;
    const int wm   = warp >> 2;
    const int wn   = warp & 3;
    const int grp  = lane >> 2;
    const int tg   = lane & 3;

    const int lrow = tid >> 3;
    const int lcol = (tid & 7) << 2;

    for (int k0 = 0; k0 < K; k0 += 32) {
        #pragma unroll
        for (int it = 0; it < 4; it++) {
            int row = lrow + it * 32;
            float4 va = *(const float4*)(A + (size_t)(m0 + row) * K + k0 + lcol);
            uint4 ua = make_uint4(f2tf(va.x), f2tf(va.y), f2tf(va.z), f2tf(va.w));
            *(uint4*)(sA + row * SM_STRIDE + lcol) = ua;
            float4 vb = *(const float4*)(B + (size_t)(n0 + row) * K + k0 + lcol);
            uint4 ub = make_uint4(f2tf(vb.x), f2tf(vb.y), f2tf(vb.z), f2tf(vb.w));
            *(uint4*)(sB + row * SM_STRIDE + lcol) = ub;
        }
        __syncthreads();

        #pragma unroll
        for (int ka = 0; ka < 4; ka++) {
            const int kb = ka * 8;
            uint32_t af[4][4], bf[4][2];
            #pragma unroll
            for (int ma = 0; ma < 4; ma++) {
                int r = wm * 64 + ma * 16 + grp;
                af[ma][0] = sA[r * SM_STRIDE + kb + tg];
                af[ma][1] = sA[(r + 8) * SM_STRIDE + kb + tg];
                af[ma][2] = sA[r * SM_STRIDE + kb + tg + 4];
                af[ma][3] = sA[(r + 8) * SM_STRIDE + kb + tg + 4];
            }
            #pragma unroll
            for (int na = 0; na < 4; na++) {
                int c = wn * 32 + na * 8 + grp;
                bf[na][0] = sB[c * SM_STRIDE + kb + tg];
                bf[na][1] = sB[c * SM_STRIDE + kb + tg + 4];
            }
            #pragma unroll
            for (int ma = 0; ma < 4; ma++)
                #pragma unroll
                for (int na = 0; na < 4; na++)
                    mma_tf32(acc[ma][na], af[ma], bf[na]);
        }
        __syncthreads();
    }
}

// ---------------------------------------------------------------------------
// Kernel 1: QKV GEMM (tf32 mma) + RoPE + scatter (unchanged from R2)
// ---------------------------------------------------------------------------
__global__ __launch_bounds__(256)
void qkv_rope_kernel(const float* __restrict__ X, const float* __restrict__ W) {
    extern __shared__ uint32_t dsm_u[];
    uint32_t* sA = dsm_u;
    uint32_t* sB = dsm_u + 128 * SM_STRIDE;
    float* sC = (float*)dsm_u;

    const int tid = threadIdx.x;
    const int m0 = blockIdx.y * 128;
    const int n0 = blockIdx.x * 128;
    const int warp = tid >> 5;
    const int lane = tid & 31;
    const int wm = warp >> 2, wn = warp & 3;
    const int grp = lane >> 2, tg = lane & 3;

    float acc[4][4][4];
    #pragma unroll
    for (int i = 0; i < 4; i++)
        #pragma unroll
        for (int j = 0; j < 4; j++)
            #pragma unroll
            for (int v = 0; v < 4; v++) acc[i][j][v] = 0.0f;

    gemm_core_tf32(X, W, m0, n0, 1024, sA, sB, acc);

    #pragma unroll
    for (int hh = 0; hh < 2; hh++) {
        if ((wn >> 1) == hh) {
            #pragma unroll
            for (int ma = 0; ma < 4; ma++) {
                int row = wm * 64 + ma * 16 + grp;
                #pragma unroll
                for (int na = 0; na < 4; na++) {
                    int col = (wn & 1) * 32 + na * 8 + 2 * tg;
                    *(float2*)(sC + row * 64 + col) =
                        make_float2(acc[ma][na][0], acc[ma][na][1]);
                    *(float2*)(sC + (row + 8) * 64 + col) =
                        make_float2(acc[ma][na][2], acc[ma][na][3]);
                }
            }
        }
        __syncthreads();

        for (int e = tid; e < 128 * 64; e += 256) {
            int r = e >> 6;
            int c = e & 63;
            int t = m0 + r;
            int b = t >> 11;
            int s = t & 2047;
            int col = n0 + hh * 64 + c;
            int head = col >> 6;
            float v = sC[r * 64 + c];
            float outv = v;
            if (head < 32) {
                float part = sC[r * 64 + (c ^ 32)];
                float rot = (c < 32) ? -part : part;
                float cs = g_cos[(s << 5) + (c & 31)];
                float sn = g_sin[(s << 5) + (c & 31)];
                outv = v * cs + rot * sn;
            }
            if (head < 16)
                g_q[(((size_t)(b * Hh + head)      << 11) + s) * 64 + c] = outv;
            else if (head < 32)
                g_k[(((size_t)(b * Hh + head - 16) << 11) + s) * 64 + c] = outv;
            else
                g_v[(((size_t)(b * Hh + head - 32) << 11) + s) * 64 + c] = outv;
        }
        __syncthreads();
    }
}

// ---------------------------------------------------------------------------
// Kernel 3: output projection + bias via tf32 mma (unchanged from R2)
// ---------------------------------------------------------------------------
__global__ __launch_bounds__(256)
void proj_kernel(const float* __restrict__ W, const float* __restrict__ bias,
                 float* __restrict__ out) {
    extern __shared__ uint32_t dsm_u[];
    uint32_t* sA = dsm_u;
    uint32_t* sB = dsm_u + 128 * SM_STRIDE;

    const int tid = threadIdx.x;
    const int m0 = blockIdx.y * 128;
    const int n0 = blockIdx.x * 128;
    const int warp = tid >> 5;
    const int lane = tid & 31;
    const int wm = warp >> 2, wn = warp & 3;
    const int grp = lane >> 2, tg = lane & 3;

    float acc[4][4][4];
    #pragma unroll
    for (int i = 0; i < 4; i++)
        #pragma unroll
        for (int j = 0; j < 4; j++)
            #pragma unroll
            for (int v = 0; v < 4; v++) acc[i][j][v] = 0.0f;

    gemm_core_tf32(g_o, W, m0, n0, 1024, sA, sB, acc);

    #pragma unroll
    for (int ma = 0; ma < 4; ma++) {
        int row = m0 + wm * 64 + ma * 16 + grp;
        #pragma unroll
        for (int na = 0; na < 4; na++) {
            int col = n0 + wn * 32 + na * 8 + 2 * tg;
            float b0 = bias[col], b1 = bias[col + 1];
            *(float2*)(out + (size_t)row * 1024 + col) =
                make_float2(acc[ma][na][0] + b0, acc[ma][na][1] + b1);
            *(float2*)(out + (size_t)(row + 8) * 1024 + col) =
                make_float2(acc[ma][na][2] + b0, acc[ma][na][3] + b1);
        }
    }
}

// ---------------------------------------------------------------------------
// Kernel 2: causal flash attention with tf32 tensor-core mma.
// Block: 128 q-rows of one (b,h). 8 warps; warp w owns rows [16w, 16w+16).
// Per kv tile (64 keys): S = Q K^T (mma), in-register online softmax
// (row stats reduce over 4 lanes), P -> smem tf32, O += P V (mma).
// Smem: sK[64][68] tf32, sV[64][68] tf32, sP[128][68] tf32 (Q staging reuses sP).
// ---------------------------------------------------------------------------
#define AKS 68   // padded stride

__global__ __launch_bounds__(256)
void attn_kernel() {
    extern __shared__ uint32_t asm_u[];
    uint32_t* sK = asm_u;                    // [64][AKS]
    uint32_t* sV = asm_u + 64 * AKS;         // [64][AKS]
    uint32_t* sP = asm_u + 2 * 64 * AKS;     // [128][AKS]; also Q staging

    const int tid  = threadIdx.x;
    const int warp = tid >> 5;
    const int lane = tid & 31;
    const int grp  = lane >> 2;    // 0..7
    const int tg   = lane & 3;     // 0..3

    const int bh = blockIdx.y;
    const int q0 = (gridDim.x - 1 - blockIdx.x) * 128;   // heavy blocks first
    const int b  = bh >> 4;
    const int h  = bh & 15;

    const float* Qg = g_q + ((size_t)bh * Ss + q0) * 64;
    const float* Kg = g_k + (size_t)bh * Ss * 64;
    const float* Vg = g_v + (size_t)bh * Ss * 64;

    // ---- stage Q (scaled by 1/8, tf32) into sP area, then pull fragments
    {
        const int r = tid >> 4;          // 0..15
        const int c = (tid & 15) << 2;   // 0..60
        #pragma unroll
        for (int i = 0; i < 8; i++) {
            int row = r + i * 16;
            float4 v = *(const float4*)(Qg + (size_t)row * 64 + c);
            uint4 u = make_uint4(f2tf(v.x * 0.125f), f2tf(v.y * 0.125f),
                                 f2tf(v.z * 0.125f), f2tf(v.w * 0.125f));
            *(uint4*)(sP + row * AKS + c) = u;
        }
    }
    __syncthreads();

    uint32_t qa[8][4];
    {
        const int r0 = warp * 16 + grp;
        #pragma unroll
        for (int ka = 0; ka < 8; ka++) {
            const int kb = ka * 8;
            qa[ka][0] = sP[r0 * AKS + kb + tg];
            qa[ka][1] = sP[(r0 + 8) * AKS + kb + tg];
            qa[ka][2] = sP[r0 * AKS + kb + tg + 4];
            qa[ka][3] = sP[(r0 + 8) * AKS + kb + tg + 4];
        }
    }

    float oacc[8][4];
    #pragma unroll
    for (int na = 0; na < 8; na++)
        #pragma unroll
        for (int v = 0; v < 4; v++) oacc[na][v] = 0.0f;
    float m0r = -1e30f, m1r = -1e30f;   // running max, rows grp / grp+8
    float l0r = 0.0f,   l1r = 0.0f;     // running sum

    const int row0g = q0 + warp * 16 + grp;   // global q row (low)
    const int row1g = row0g + 8;              // global q row (high)

    for (int kv0 = 0; kv0 < q0 + 128; kv0 += 64) {
        __syncthreads();   // prior tile's reads of sK/sV/sP done

        // ---- load K,V tiles -> tf32 smem
        {
            const int r = tid >> 4;
            const int c = (tid & 15) << 2;
            #pragma unroll
            for (int i = 0; i < 4; i++) {
                int row = r + i * 16;
                float4 kk = *(const float4*)(Kg + (size_t)(kv0 + row) * 64 + c);
                *(uint4*)(sK + row * AKS + c) =
                    make_uint4(f2tf(kk.x), f2tf(kk.y), f2tf(kk.z), f2tf(kk.w));
                float4 vv = *(const float4*)(Vg + (size_t)(kv0 + row) * 64 + c);
                *(uint4*)(sV + row * AKS + c) =
                    make_uint4(f2tf(vv.x), f2tf(vv.y), f2tf(vv.z), f2tf(vv.w));
            }
        }
        __syncthreads();

        // ---- S = Q K^T  (scores pre-scaled via Q)
        float sacc[8][4];
        #pragma unroll
        for (int na = 0; na < 8; na++)
            #pragma unroll
            for (int v = 0; v < 4; v++) sacc[na][v] = 0.0f;

        #pragma unroll
        for (int ka = 0; ka < 8; ka++) {
            const int kb = ka * 8;
            #pragma unroll
            for (int na = 0; na < 8; na++) {
                uint32_t bf[2];
                bf[0] = sK[(na * 8 + grp) * AKS + kb + tg];
                bf[1] = sK[(na * 8 + grp) * AKS + kb + tg + 4];
                mma_tf32(sacc[na], qa[ka], bf);
            }
        }

        // ---- causal mask (only final two tiles need it)
        if (kv0 + 64 > q0) {
            #pragma unroll
            for (int na = 0; na < 8; na++) {
                int c0 = kv0 + na * 8 + 2 * tg;
                if (c0     > row0g) sacc[na][0] = -1e30f;
                if (c0 + 1 > row0g) sacc[na][1] = -1e30f;
                if (c0     > row1g) sacc[na][2] = -1e30f;
                if (c0 + 1 > row1g) sacc[na][3] = -1e30f;
            }
        }

        // ---- online softmax: row max over 16 cols + 4-lane butterfly
        float tm0 = -1e30f, tm1 = -1e30f;
        #pragma unroll
        for (int na = 0; na < 8; na++) {
            tm0 = fmaxf(tm0, fmaxf(sacc[na][0], sacc[na][1]));
            tm1 = fmaxf(tm1, fmaxf(sacc[na][2], sacc[na][3]));
        }
        tm0 = fmaxf(tm0, __shfl_xor_sync(0xffffffffu, tm0, 1));
        tm0 = fmaxf(tm0, __shfl_xor_sync(0xffffffffu, tm0, 2));
        tm1 = fmaxf(tm1, __shfl_xor_sync(0xffffffffu, tm1, 1));
        tm1 = fmaxf(tm1, __shfl_xor_sync(0xffffffffu, tm1, 2));

        float mn0 = fmaxf(m0r, tm0);
        float mn1 = fmaxf(m1r, tm1);
        float al0 = __expf(m0r - mn0);
        float al1 = __expf(m1r - mn1);
        m0r = mn0; m1r = mn1;

        float rs0 = 0.0f, rs1 = 0.0f;
        #pragma unroll
        for (int na = 0; na < 8; na++) {
            sacc[na][0] = __expf(sacc[na][0] - mn0);
            sacc[na][1] = __expf(sacc[na][1] - mn0);
            sacc[na][2] = __expf(sacc[na][2] - mn1);
            sacc[na][3] = __expf(sacc[na][3] - mn1);
            rs0 += sacc[na][0] + sacc[na][1];
            rs1 += sacc[na][2] + sacc[na][3];
        }
        rs0 += __shfl_xor_sync(0xffffffffu, rs0, 1);
        rs0 += __shfl_xor_sync(0xffffffffu, rs0, 2);
        rs1 += __shfl_xor_sync(0xffffffffu, rs1, 1);
        rs1 += __shfl_xor_sync(0xffffffffu, rs1, 2);
        l0r = l0r * al0 + rs0;
        l1r = l1r * al1 + rs1;

        #pragma unroll
        for (int na = 0; na < 8; na++) {
            oacc[na][0] *= al0; oacc[na][1] *= al0;
            oacc[na][2] *= al1; oacc[na][3] *= al1;
        }

        // ---- P -> smem (tf32), warp-private rows
        {
            const int r0 = warp * 16 + grp;
            #pragma unroll
            for (int na = 0; na < 8; na++) {
                int c0 = na * 8 + 2 * tg;
                *(uint2*)(sP + r0 * AKS + c0) =
                    make_uint2(f2tf(sacc[na][0]), f2tf(sacc[na][1]));
                *(uint2*)(sP + (r0 + 8) * AKS + c0) =
                    make_uint2(f2tf(sacc[na][2]), f2tf(sacc[na][3]));
            }
        }
        __syncwarp();

        // ---- O += P V
        {
            const int r0 = warp * 16 + grp;
            #pragma unroll
            for (int ka = 0; ka < 8; ka++) {
                const int kb = ka * 8;
                uint32_t pa[4];
                pa[0] = sP[r0 * AKS + kb + tg];
                pa[1] = sP[(r0 + 8) * AKS + kb + tg];
                pa[2] = sP[r0 * AKS + kb + tg + 4];
                pa[3] = sP[(r0 + 8) * AKS + kb + tg + 4];
                #pragma unroll
                for (int na = 0; na < 8; na++) {
                    uint32_t bf[2];
                    bf[0] = sV[(kb + tg) * AKS + na * 8 + grp];
                    bf[1] = sV[(kb + tg + 4) * AKS + na * 8 + grp];
                    mma_tf32(oacc[na], pa, bf);
                }
            }
        }
    }

    // ---- normalize + write
    {
        float inv0 = 1.0f / l0r;
        float inv1 = 1.0f / l1r;
        float* O0 = g_o + ((size_t)(b * Ss) + row0g) * 1024 + h * 64;
        float* O1 = g_o + ((size_t)(b * Ss) + row1g) * 1024 + h * 64;
        #pragma unroll
        for (int na = 0; na < 8; na++) {
            int c0 = na * 8 + 2 * tg;
            *(float2*)(O0 + c0) = make_float2(oacc[na][0] * inv0,
                                              oacc[na][1] * inv0);
            *(float2*)(O1 + c0) = make_float2(oacc[na][2] * inv1,
                                              oacc[na][3] * inv1);
        }
    }
}

// ---------------------------------------------------------------------------
extern "C" void kernel_launch(void* const* d_in, const int* in_sizes, int n_in,
                              void* d_out, int out_size) {
    const float* x     = (const float*)d_in[0];
    const float* w_qkv = (const float*)d_in[1];
    const float* w_out = (const float*)d_in[2];
    const float* b_out = (const float*)d_in[3];
    float* out = (float*)d_out;

    rope_table_kernel<<<(Ss * 32 + 255) / 256, 256>>>();

    const int gemm_smem = 2 * 128 * SM_STRIDE * (int)sizeof(uint32_t); // 36864
    qkv_rope_kernel<<<dim3(E3 / 128, Tt / 128), 256, gemm_smem>>>(x, w_qkv);

    const int attn_smem = (2 * 64 * AKS + 128 * AKS) * (int)sizeof(uint32_t); // 69632
    cudaFuncSetAttribute(attn_kernel,
                         cudaFuncAttributeMaxDynamicSharedMemorySize, attn_smem);
    attn_kernel<<<dim3(Ss / 128, Bb * Hh), 256, attn_smem>>>();

    proj_kernel<<<dim3(Dd / 128, Tt / 128), 256, gemm_smem>>>(w_out, b_out, out);
}